// round 3
// baseline (speedup 1.0000x reference)
#include <cuda_runtime.h>
#include <math.h>

#define MAXN 8192
#define THREADS 128
#define QPT 8                    // queries per thread = 4 packed f32x2 chains
#define NCH (QPT / 2)
#define QBLK (THREADS * QPT)     // 1024 queries per block
#define SLAB 256                 // DB points per slab

// Scratch (allocation-free rule).
__device__ float4 g_ref4[MAXN];              // (x,y,z,sigma)
__device__ float4 g_src4[MAXN];              // transformed (x,y,z,sigma)
__device__ unsigned long long g_fwd[MAXN];   // (dist2_bits<<32)|sigma_bits
__device__ unsigned long long g_bwd[MAXN];

static __device__ __forceinline__ unsigned long long pack2(float lo, float hi) {
    unsigned long long r;
    asm("mov.b64 %0, {%1, %2};" : "=l"(r) : "f"(lo), "f"(hi));
    return r;
}
static __device__ __forceinline__ unsigned long long fma2(
    unsigned long long a, unsigned long long b, unsigned long long c) {
    unsigned long long r;
    asm("fma.rn.f32x2 %0, %1, %2, %3;" : "=l"(r) : "l"(a), "l"(b), "l"(c));
    return r;
}
static __device__ __forceinline__ void unpack2(unsigned long long v, float& lo, float& hi) {
    asm("mov.b64 {%0, %1}, %2;" : "=f"(lo), "=f"(hi) : "l"(v));
}

__global__ void init_kernel(const float* __restrict__ ref,
                            const float* __restrict__ src,
                            const float* __restrict__ T,
                            const float* __restrict__ rsig,
                            const float* __restrict__ ssig,
                            int n, int m) {
    int i = blockIdx.x * blockDim.x + threadIdx.x;
    if (i < n) {
        g_ref4[i] = make_float4(ref[3*i], ref[3*i+1], ref[3*i+2], rsig[i]);
        g_fwd[i] = ~0ULL;
    }
    if (i < m) {
        float x = src[3*i], y = src[3*i+1], z = src[3*i+2];
        float X = T[0]*x + T[1]*y + T[2]*z  + T[3];
        float Y = T[4]*x + T[5]*y + T[6]*z  + T[7];
        float Z = T[8]*x + T[9]*y + T[10]*z + T[11];
        g_src4[i] = make_float4(X, Y, Z, ssig[i]);
        g_bwd[i] = ~0ULL;
    }
}

// blockIdx.z == 0: queries=ref, DB=src (forward). z == 1: swapped (backward).
// Inner metric: d' = |b|^2 - 2 a.b  (query-constant |a|^2 dropped: argmin-safe).
// Slab pre-duplicated into f32x2 lanes so FFMA2 processes 2 queries/instr.
__global__ void __launch_bounds__(THREADS) nn_kernel(int n, int m) {
    int dir = blockIdx.z;
    const float4* __restrict__ A = dir ? g_src4 : g_ref4;
    const float4* __restrict__ B = dir ? g_ref4 : g_src4;
    unsigned long long* __restrict__ keys = dir ? g_bwd : g_fwd;
    int nA = dir ? m : n;
    int nB = dir ? n : m;

    __shared__ ulonglong2 sBp[SLAB * 2];   // {(-2x? no: x,x),(y,y)} , {(z,z),(b2,b2)}
    __shared__ float4 sBo[SLAB];           // original (x,y,z,sigma) for epilogue
    int tid = threadIdx.x;
    int jbase = blockIdx.y * SLAB;

    for (int j = tid; j < SLAB; j += THREADS) {
        int gj = jbase + j;
        float4 b = (gj < nB) ? B[gj] : make_float4(1e15f, 1e15f, 1e15f, 1.0f);
        sBo[j] = b;
        float nx = -2.0f * b.x, ny = -2.0f * b.y, nz = -2.0f * b.z;
        float b2 = fmaf(b.x, b.x, fmaf(b.y, b.y, b.z * b.z));
        sBp[2*j + 0] = make_ulonglong2(pack2(nx, nx), pack2(ny, ny));
        sBp[2*j + 1] = make_ulonglong2(pack2(nz, nz), pack2(b2, b2));
    }

    unsigned long long axp[NCH], ayp[NCH], azp[NCH];
    float bd[QPT];
    int   bj[QPT];
    int q0 = blockIdx.x * QBLK + tid;
#pragma unroll
    for (int c = 0; c < NCH; c++) {
        int qi0 = q0 + (2*c + 0) * THREADS;
        int qi1 = q0 + (2*c + 1) * THREADS;
        float4 a0 = (qi0 < nA) ? A[qi0] : make_float4(0.f, 0.f, 0.f, 0.f);
        float4 a1 = (qi1 < nA) ? A[qi1] : make_float4(0.f, 0.f, 0.f, 0.f);
        axp[c] = pack2(a0.x, a1.x);
        ayp[c] = pack2(a0.y, a1.y);
        azp[c] = pack2(a0.z, a1.z);
        bd[2*c] = 3.4e38f; bd[2*c+1] = 3.4e38f;
        bj[2*c] = 0;       bj[2*c+1] = 0;
    }
    __syncthreads();

#pragma unroll 4
    for (int j = 0; j < SLAB; j++) {
        ulonglong2 u0 = sBp[2*j + 0];   // (x,x),(y,y) scaled by -2
        ulonglong2 u1 = sBp[2*j + 1];   // (z,z),(b2,b2)
#pragma unroll
        for (int c = 0; c < NCH; c++) {
            unsigned long long t = fma2(azp[c], u1.x, u1.y);
            t = fma2(ayp[c], u0.y, t);
            t = fma2(axp[c], u0.x, t);
            float d0, d1;
            unpack2(t, d0, d1);
            bool p0 = d0 < bd[2*c + 0];
            bool p1 = d1 < bd[2*c + 1];
            bd[2*c + 0] = p0 ? d0 : bd[2*c + 0];
            bj[2*c + 0] = p0 ? j  : bj[2*c + 0];
            bd[2*c + 1] = p1 ? d1 : bd[2*c + 1];
            bj[2*c + 1] = p1 ? j  : bj[2*c + 1];
        }
    }

    // Epilogue: exact non-negative dist^2 for winner, pack with its sigma.
#pragma unroll
    for (int c = 0; c < NCH; c++) {
        float ax0, ax1, ay0, ay1, az0, az1;
        unpack2(axp[c], ax0, ax1);
        unpack2(ayp[c], ay0, ay1);
        unpack2(azp[c], az0, az1);
#pragma unroll
        for (int h = 0; h < 2; h++) {
            int q = 2*c + h;
            int qi = q0 + q * THREADS;
            if (qi < nA) {
                float ax = h ? ax1 : ax0, ay = h ? ay1 : ay0, az = h ? az1 : az0;
                float4 b = sBo[bj[q]];
                float dx = ax - b.x, dy = ay - b.y, dz = az - b.z;
                float d2 = fmaf(dx, dx, fmaf(dy, dy, dz * dz));
                unsigned long long key =
                    (((unsigned long long)__float_as_uint(d2)) << 32) |
                    (unsigned long long)__float_as_uint(b.w);
                atomicMin(&keys[qi], key);
            }
        }
    }
}

// One 1024-thread block: both directions summed + finalized in one launch.
__global__ void __launch_bounds__(1024) reduce_kernel(float* __restrict__ out,
                                                      int n, int m) {
    __shared__ float wsum[32];
    int tid = threadIdx.x;
    float inv_n = 1.0f / (float)n;
    float inv_m = 1.0f / (float)m;
    float acc = 0.0f;
    for (int i = tid; i < n; i += 1024) {
        unsigned long long k = g_fwd[i];
        float d   = sqrtf(__uint_as_float((unsigned)(k >> 32)));
        float sig = 0.5f * (g_ref4[i].w + __uint_as_float((unsigned)k));
        acc += (__logf(sig) + __fdividef(d, sig)) * inv_n;
    }
    for (int i = tid; i < m; i += 1024) {
        unsigned long long k = g_bwd[i];
        float d   = sqrtf(__uint_as_float((unsigned)(k >> 32)));
        float sig = 0.5f * (g_src4[i].w + __uint_as_float((unsigned)k));
        acc += (__logf(sig) + __fdividef(d, sig)) * inv_m;
    }
#pragma unroll
    for (int o = 16; o > 0; o >>= 1)
        acc += __shfl_xor_sync(0xFFFFFFFF, acc, o);
    if ((tid & 31) == 0) wsum[tid >> 5] = acc;
    __syncthreads();
    if (tid < 32) {
        float v = wsum[tid];
#pragma unroll
        for (int o = 16; o > 0; o >>= 1)
            v += __shfl_xor_sync(0xFFFFFFFF, v, o);
        if (tid == 0) out[0] = v;
    }
}

extern "C" void kernel_launch(void* const* d_in, const int* in_sizes, int n_in,
                              void* d_out, int out_size) {
    const float* ref  = (const float*)d_in[0];
    const float* src  = (const float*)d_in[1];
    const float* T    = (const float*)d_in[2];
    const float* rsig = (const float*)d_in[3];
    const float* ssig = (const float*)d_in[4];
    int n = in_sizes[3];
    int m = in_sizes[4];

    int nm = n > m ? n : m;
    init_kernel<<<(nm + 255) / 256, 256>>>(ref, src, T, rsig, ssig, n, m);

    dim3 g((nm + QBLK - 1) / QBLK, (nm + SLAB - 1) / SLAB, 2);
    nn_kernel<<<g, THREADS>>>(n, m);

    reduce_kernel<<<1, 1024>>>((float*)d_out, n, m);
}